// round 15
// baseline (speedup 1.0000x reference)
#include <cuda_runtime.h>
#include <cuda_fp16.h>
#include <cstdint>

#define MOD_SCALE 0.04419417382415922f   /* 1/sqrt(512) */
#define CONV_SCALE 0.014731391274719739f /* 1/sqrt(512*9) */

// ---------------- device scratch ----------------
// Winograd F(2x2,3x3): 16 transform points, 16384 tiles (16 batch x 32 x 32), 512 ci/co.
__device__ float  g_s[16 * 512];
__device__ float  g_W2[512 * 512];
__device__ float  g_alpha[16 * 512];
__device__ __align__(16) __half g_U[16 * 512 * 512];          // [p][co][ci]   8.4 MB
__device__ __align__(16) __half g_V[134217728];               // [p][tile][ci] 268 MB
__device__ __align__(16) __half g_M[134217728];               // [p][co][tile] 268 MB (fp16)

#define VPLANE 8388608   /* 16384*512 */
#define MPLANE 8388608   /* 512*16384 */

// ---------------- kernel A: mod s (blocks 0-1023) + weight transform U + W2 ----------------
__global__ void prepA_kernel(const float* __restrict__ style,
                             const float* __restrict__ mw,
                             const float* __restrict__ bias,
                             const float* __restrict__ weight) {
    if (blockIdx.x < 1024) {
        int warp = (blockIdx.x * 256 + threadIdx.x) >> 5;
        int lane = threadIdx.x & 31;
        int b = warp >> 9, ci = warp & 511;
        float sum = 0.f;
        const float* st = style + b * 512;
        const float* w  = mw + ci * 512;
        for (int d = lane; d < 512; d += 32) sum += st[d] * w[d];
        #pragma unroll
        for (int off = 16; off > 0; off >>= 1) sum += __shfl_xor_sync(0xffffffffu, sum, off);
        if (lane == 0) g_s[b * 512 + ci] = sum * MOD_SCALE + bias[ci];
    } else {
        int idx = (blockIdx.x - 1024) * 256 + threadIdx.x;  // co*512+ci
        const float* w = weight + (size_t)idx * 9;
        float g[3][3];
        float s2 = 0.f;
        #pragma unroll
        for (int k = 0; k < 9; k++) {
            float v = w[k];
            s2 += v * v;
            g[k / 3][k % 3] = v;
        }
        g_W2[idx] = s2;
        float T[4][3];
        #pragma unroll
        for (int j = 0; j < 3; j++) {
            T[0][j] = g[0][j];
            T[1][j] = 0.5f * (g[0][j] + g[1][j] + g[2][j]);
            T[2][j] = 0.5f * (g[0][j] - g[1][j] + g[2][j]);
            T[3][j] = g[2][j];
        }
        #pragma unroll
        for (int i = 0; i < 4; i++) {
            float u0 = T[i][0];
            float u1 = 0.5f * (T[i][0] + T[i][1] + T[i][2]);
            float u2 = 0.5f * (T[i][0] - T[i][1] + T[i][2]);
            float u3 = T[i][2];
            g_U[(size_t)(i * 4 + 0) * 262144 + idx] = __float2half(u0);
            g_U[(size_t)(i * 4 + 1) * 262144 + idx] = __float2half(u1);
            g_U[(size_t)(i * 4 + 2) * 262144 + idx] = __float2half(u2);
            g_U[(size_t)(i * 4 + 3) * 262144 + idx] = __float2half(u3);
        }
    }
}

// ---------------- kernel B: alpha (blocks 0-1023) + input transform V ----------------
__global__ void prepB_kernel(const float* __restrict__ x) {
    if (blockIdx.x < 1024) {
        int warp = (blockIdx.x * 256 + threadIdx.x) >> 5;
        int lane = threadIdx.x & 31;
        int b = warp >> 9, co = warp & 511;
        float sum = 0.f;
        const float* w2 = g_W2 + co * 512;
        const float* sv = g_s + b * 512;
        for (int ci = lane; ci < 512; ci += 32) {
            float s = sv[ci];
            sum += w2[ci] * s * s;
        }
        #pragma unroll
        for (int off = 16; off > 0; off >>= 1) sum += __shfl_xor_sync(0xffffffffu, sum, off);
        if (lane == 0)
            g_alpha[b * 512 + co] = CONV_SCALE / sqrtf(CONV_SCALE * CONV_SCALE * sum + 1e-8f);
        return;
    }
    __shared__ float smx[4][66][33];
    __shared__ float ss[32];
    int id = blockIdx.x - 1024;                 // 8192 blocks
    int ty = id & 31, ci0 = ((id >> 5) & 15) * 32, b = id >> 9;
    int tid = threadIdx.x;
    for (int k = tid; k < 4 * 66 * 33; k += 256) (&smx[0][0][0])[k] = 0.f;
    if (tid < 32) ss[tid] = g_s[b * 512 + ci0 + tid];
    __syncthreads();
    {
        int i = tid >> 3, r = tid & 7;
        int yl = r >> 1, xh = (r & 1) * 32;
        int ygl = 2 * ty - 1 + yl;
        if (ygl >= 0 && ygl < 64) {
            float s = ss[i];
            const float4* src = reinterpret_cast<const float4*>(
                x + ((size_t)(b * 512 + ci0 + i) * 64 + ygl) * 64 + xh);
            #pragma unroll
            for (int k = 0; k < 8; k++) {
                float4 f = src[k];
                int c = xh + k * 4 + 1;
                smx[yl][c + 0][i] = f.x * s;
                smx[yl][c + 1][i] = f.y * s;
                smx[yl][c + 2][i] = f.z * s;
                smx[yl][c + 3][i] = f.w * s;
            }
        }
    }
    __syncthreads();
    int lane = tid & 31, w = tid >> 5;
    size_t tbase = ((size_t)(b * 32 + ty)) * 32;
    #pragma unroll
    for (int it = 0; it < 4; it++) {
        int tx = w + it * 8;
        float d[4][4];
        #pragma unroll
        for (int i = 0; i < 4; i++)
            #pragma unroll
            for (int j = 0; j < 4; j++)
                d[i][j] = smx[i][2 * tx + j][lane];
        float e[4][4];
        #pragma unroll
        for (int j = 0; j < 4; j++) {
            e[0][j] = d[0][j] - d[2][j];
            e[1][j] = d[1][j] + d[2][j];
            e[2][j] = d[2][j] - d[1][j];
            e[3][j] = d[1][j] - d[3][j];
        }
        size_t vofs = (tbase + tx) * 512 + ci0 + lane;
        #pragma unroll
        for (int i = 0; i < 4; i++) {
            float v0 = e[i][0] - e[i][2];
            float v1 = e[i][1] + e[i][2];
            float v2 = e[i][2] - e[i][1];
            float v3 = e[i][1] - e[i][3];
            g_V[(size_t)(i * 4 + 0) * VPLANE + vofs] = __float2half(v0);
            g_V[(size_t)(i * 4 + 1) * VPLANE + vofs] = __float2half(v1);
            g_V[(size_t)(i * 4 + 2) * VPLANE + vofs] = __float2half(v2);
            g_V[(size_t)(i * 4 + 3) * VPLANE + vofs] = __float2half(v3);
        }
    }
}

// ================= GEMM kernel: 4 planes per CTA, continuous 16-stage pipeline =================
// CTA: 128 co x 256 tiles at fixed (co0, n0), p = pbase..pbase+3.
// Global stage g=0..15: plane = g>>2, kc = g&3. Double-buffered fills run across
// plane boundaries; acc dumped to M[plane] (fp16) and zeroed every 4 stages.

#define GSTRIDE 136
#define GB_BYTES (256 * GSTRIDE * 2)   /* 69632 */
#define GA_BYTES (128 * GSTRIDE * 2)   /* 34816 */
#define GSTG (GB_BYTES + GA_BYTES)     /* 104448 */
#define GSMEM (2 * GSTG)               /* 208896 */

__device__ __forceinline__ void cp16(uint32_t dst, const void* src, int sz) {
    asm volatile("cp.async.cg.shared.global [%0], [%1], 16, %2;"
                 :: "r"(dst), "l"(src), "r"(sz) : "memory");
}
__device__ __forceinline__ void cp_commit() {
    asm volatile("cp.async.commit_group;" ::: "memory");
}
__device__ __forceinline__ void ldsm4(uint32_t r[4], uint32_t addr) {
    asm volatile("ldmatrix.sync.aligned.m8n8.x4.shared.b16 {%0,%1,%2,%3}, [%4];"
                 : "=r"(r[0]), "=r"(r[1]), "=r"(r[2]), "=r"(r[3]) : "r"(addr));
}
__device__ __forceinline__ void mma_f16(float acc[4], const uint32_t a[4], const uint32_t b2[2]) {
    asm volatile(
        "mma.sync.aligned.m16n8k16.row.col.f32.f16.f16.f32 "
        "{%0,%1,%2,%3}, {%4,%5,%6,%7}, {%8,%9}, {%0,%1,%2,%3};\n"
        : "+f"(acc[0]), "+f"(acc[1]), "+f"(acc[2]), "+f"(acc[3])
        : "r"(a[0]), "r"(a[1]), "r"(a[2]), "r"(a[3]), "r"(b2[0]), "r"(b2[1]));
}

__global__ void __launch_bounds__(256, 1) gemm_kernel() {
    extern __shared__ __align__(16) __half sh[];
    const uint32_t sbase = (uint32_t)__cvta_generic_to_shared(sh);

    const int tid = threadIdx.x, lane = tid & 31, warp = tid >> 5;
    const int wm = warp & 3, wn = warp >> 2;
    const int pbase = blockIdx.z * 4, co0 = blockIdx.x * 128, n0 = blockIdx.y * 256;

    // fill global stage g into buffer buf
    auto fill = [&](int g, int buf) {
        int pl = pbase + (g >> 2);
        const __half* Vp = g_V + (size_t)pl * VPLANE;
        const __half* Up = g_U + (size_t)pl * 262144;
        uint32_t bb_ = sbase + buf * GSTG;
        uint32_t ab_ = bb_ + GB_BYTES;
        int ofs = (g & 3) * 128;
        #pragma unroll
        for (int it = 0; it < 16; it++) {          // B: 256 rows x 16 cp
            int idx = tid + it * 256;
            int row = idx >> 4, v = idx & 15;
            cp16(bb_ + (uint32_t)(row * GSTRIDE + v * 8) * 2,
                 Vp + (size_t)(n0 + row) * 512 + ofs + v * 8, 16);
        }
        #pragma unroll
        for (int it = 0; it < 8; it++) {           // A: 128 rows x 16 cp
            int idx = tid + it * 256;
            int row = idx >> 4, v = idx & 15;
            cp16(ab_ + (uint32_t)(row * GSTRIDE + v * 8) * 2,
                 Up + (size_t)(co0 + row) * 512 + ofs + v * 8, 16);
        }
        cp_commit();
    };

    const int l15 = ((lane >> 3) & 1) * 8 + (lane & 7);
    const int aK  = (lane >> 4) * 8;
    uint32_t aBase[2];
    #pragma unroll
    for (int mf = 0; mf < 2; mf++)
        aBase[mf] = (uint32_t)(((wm * 32 + mf * 16 + l15) * GSTRIDE + aK) * 2);
    const int nloc = ((lane >> 4) & 1) * 8 + (lane & 7);
    const int bK   = ((lane >> 3) & 1) * 8;
    uint32_t bBase[8];
    #pragma unroll
    for (int nfp = 0; nfp < 8; nfp++)
        bBase[nfp] = (uint32_t)(((wn * 128 + nfp * 16 + nloc) * GSTRIDE + bK) * 2);

    float acc[2][16][4];
    #pragma unroll
    for (int mf = 0; mf < 2; mf++)
        #pragma unroll
        for (int nf = 0; nf < 16; nf++)
            #pragma unroll
            for (int i = 0; i < 4; i++) acc[mf][nf][i] = 0.f;

    fill(0, 0);
    fill(1, 1);

    for (int g = 0; g < 16; g++) {
        if (g < 15) asm volatile("cp.async.wait_group 1;" ::: "memory");
        else        asm volatile("cp.async.wait_group 0;" ::: "memory");
        __syncthreads();

        const uint32_t bB = sbase + (g & 1) * GSTG;
        const uint32_t aB = bB + GB_BYTES;

        #define AOFS(t, h) (aB + aBase[h] + (uint32_t)((t) * 32))
        #define BOFS(t, nfp) (bB + bBase[nfp] + (uint32_t)((t) * 32))

        uint32_t aa[2][2][4];
        uint32_t bb[2][4];
        ldsm4(aa[0][0], AOFS(0, 0));
        ldsm4(aa[0][1], AOFS(0, 1));
        ldsm4(bb[0], BOFS(0, 0));

        #pragma unroll
        for (int t = 0; t < 8; t++) {
            const int ct = t & 1, nt = ct ^ 1;
            if (t < 7) {
                ldsm4(aa[nt][0], AOFS(t + 1, 0));
                ldsm4(aa[nt][1], AOFS(t + 1, 1));
            }
            #pragma unroll
            for (int nfp = 0; nfp < 8; nfp++) {
                const int cb = nfp & 1, nb = cb ^ 1;
                if (nfp < 7)     ldsm4(bb[nb], BOFS(t, nfp + 1));
                else if (t < 7)  ldsm4(bb[nb], BOFS(t + 1, 0));
                mma_f16(acc[0][2 * nfp],     aa[ct][0], bb[cb]);
                mma_f16(acc[0][2 * nfp + 1], aa[ct][0], bb[cb] + 2);
                mma_f16(acc[1][2 * nfp],     aa[ct][1], bb[cb]);
                mma_f16(acc[1][2 * nfp + 1], aa[ct][1], bb[cb] + 2);
            }
        }
        #undef AOFS
        #undef BOFS

        __syncthreads();
        if (g + 2 < 16) fill(g + 2, g & 1);

        // end of plane: dump acc to M[plane] (fp16) and reset — overlaps in-flight fill
        if ((g & 3) == 3) {
            int pl = pbase + (g >> 2);
            __half* Mp = g_M + (size_t)pl * MPLANE;
            #pragma unroll
            for (int mf = 0; mf < 2; mf++) {
                int co = co0 + wm * 32 + mf * 16 + (lane >> 2);
                __half* m0 = Mp + (size_t)co * 16384;
                __half* m1 = m0 + 8 * 16384;
                #pragma unroll
                for (int nf = 0; nf < 16; nf++) {
                    int tile = n0 + wn * 128 + nf * 8 + (lane & 3) * 2;
                    *reinterpret_cast<__half2*>(m0 + tile) =
                        __floats2half2_rn(acc[mf][nf][0], acc[mf][nf][1]);
                    *reinterpret_cast<__half2*>(m1 + tile) =
                        __floats2half2_rn(acc[mf][nf][2], acc[mf][nf][3]);
                    #pragma unroll
                    for (int i = 0; i < 4; i++) acc[mf][nf][i] = 0.f;
                }
            }
        }
    }
}

// ---------------- output transform: y = A^T M A (fp16 M, tile-pairs via half2) ----------------
__global__ void outT_kernel(float* __restrict__ out) {
    int id = blockIdx.x * 256 + threadIdx.x;    // 4.2M threads (tile pairs)
    int txp = id & 15, ty = (id >> 4) & 31, b = (id >> 9) & 15, co = id >> 13;
    size_t mo = (size_t)co * 16384 + ((size_t)(b * 32 + ty)) * 32 + 2 * txp;
    float2 m[16];
    #pragma unroll
    for (int q = 0; q < 16; q++)
        m[q] = __half22float2(*reinterpret_cast<const __half2*>(g_M + (size_t)q * MPLANE + mo));
    float a = g_alpha[b * 512 + co];
    float4 row0, row1;
    {
        float s0[4], s1[4];
        #pragma unroll
        for (int j = 0; j < 4; j++) {
            s0[j] = m[j].x + m[4 + j].x + m[8 + j].x;
            s1[j] = m[4 + j].x - m[8 + j].x - m[12 + j].x;
        }
        row0.x = a * (s0[0] + s0[1] + s0[2]); row0.y = a * (s0[1] - s0[2] - s0[3]);
        row1.x = a * (s1[0] + s1[1] + s1[2]); row1.y = a * (s1[1] - s1[2] - s1[3]);
    }
    {
        float s0[4], s1[4];
        #pragma unroll
        for (int j = 0; j < 4; j++) {
            s0[j] = m[j].y + m[4 + j].y + m[8 + j].y;
            s1[j] = m[4 + j].y - m[8 + j].y - m[12 + j].y;
        }
        row0.z = a * (s0[0] + s0[1] + s0[2]); row0.w = a * (s0[1] - s0[2] - s0[3]);
        row1.z = a * (s1[0] + s1[1] + s1[2]); row1.w = a * (s1[1] - s1[2] - s1[3]);
    }
    float* o = out + (((size_t)(b * 512 + co) * 64 + 2 * ty) * 64 + 4 * txp);
    *reinterpret_cast<float4*>(o)      = row0;
    *reinterpret_cast<float4*>(o + 64) = row1;
}

// ---------------- launch ----------------
extern "C" void kernel_launch(void* const* d_in, const int* in_sizes, int n_in,
                              void* d_out, int out_size) {
    const float* x     = (const float*)d_in[0];
    const float* style = (const float*)d_in[1];
    const float* weight= (const float*)d_in[2];
    const float* mw    = (const float*)d_in[3];
    const float* mbias = (const float*)d_in[4];
    float* out = (float*)d_out;
    (void)in_sizes; (void)n_in; (void)out_size;

    cudaFuncSetAttribute(gemm_kernel, cudaFuncAttributeMaxDynamicSharedMemorySize, GSMEM);

    prepA_kernel<<<2048, 256>>>(style, mw, mbias, weight);
    prepB_kernel<<<1024 + 8192, 256>>>(x);
    gemm_kernel<<<dim3(4, 64, 4), 256, GSMEM>>>();
    outT_kernel<<<16384, 256>>>(out);
}

// round 17
// speedup vs baseline: 1.0004x; 1.0004x over previous
#include <cuda_runtime.h>
#include <cuda_fp16.h>
#include <cstdint>

#define MOD_SCALE 0.04419417382415922f   /* 1/sqrt(512) */
#define CONV_SCALE 0.014731391274719739f /* 1/sqrt(512*9) */

// ---------------- device scratch ----------------
// Winograd F(2x2,3x3): 16 transform points, 16384 tiles (16 batch x 32 x 32), 512 ci/co.
__device__ float  g_s[16 * 512];
__device__ float  g_W2[512 * 512];
__device__ float  g_alpha[16 * 512];
__device__ __align__(16) __half g_U[16 * 512 * 512];          // [p][co][ci]   8.4 MB
__device__ __align__(16) __half g_V[134217728];               // [p][tile][ci] 268 MB
__device__ __align__(16) __half g_M[134217728];               // [p][co][tile] 268 MB (fp16)

#define VPLANE 8388608   /* 16384*512 */
#define MPLANE 8388608   /* 512*16384 */

// ---------------- kernel A: mod s (blocks 0-1023) + weight transform U + W2 ----------------
__global__ void prepA_kernel(const float* __restrict__ style,
                             const float* __restrict__ mw,
                             const float* __restrict__ bias,
                             const float* __restrict__ weight) {
    if (blockIdx.x < 1024) {
        int warp = (blockIdx.x * 256 + threadIdx.x) >> 5;
        int lane = threadIdx.x & 31;
        int b = warp >> 9, ci = warp & 511;
        float sum = 0.f;
        const float* st = style + b * 512;
        const float* w  = mw + ci * 512;
        for (int d = lane; d < 512; d += 32) sum += st[d] * w[d];
        #pragma unroll
        for (int off = 16; off > 0; off >>= 1) sum += __shfl_xor_sync(0xffffffffu, sum, off);
        if (lane == 0) g_s[b * 512 + ci] = sum * MOD_SCALE + bias[ci];
    } else {
        int idx = (blockIdx.x - 1024) * 256 + threadIdx.x;  // co*512+ci
        const float* w = weight + (size_t)idx * 9;
        float g[3][3];
        float s2 = 0.f;
        #pragma unroll
        for (int k = 0; k < 9; k++) {
            float v = w[k];
            s2 += v * v;
            g[k / 3][k % 3] = v;
        }
        g_W2[idx] = s2;
        float T[4][3];
        #pragma unroll
        for (int j = 0; j < 3; j++) {
            T[0][j] = g[0][j];
            T[1][j] = 0.5f * (g[0][j] + g[1][j] + g[2][j]);
            T[2][j] = 0.5f * (g[0][j] - g[1][j] + g[2][j]);
            T[3][j] = g[2][j];
        }
        #pragma unroll
        for (int i = 0; i < 4; i++) {
            float u0 = T[i][0];
            float u1 = 0.5f * (T[i][0] + T[i][1] + T[i][2]);
            float u2 = 0.5f * (T[i][0] - T[i][1] + T[i][2]);
            float u3 = T[i][2];
            g_U[(size_t)(i * 4 + 0) * 262144 + idx] = __float2half(u0);
            g_U[(size_t)(i * 4 + 1) * 262144 + idx] = __float2half(u1);
            g_U[(size_t)(i * 4 + 2) * 262144 + idx] = __float2half(u2);
            g_U[(size_t)(i * 4 + 3) * 262144 + idx] = __float2half(u3);
        }
    }
}

// ---------------- kernel B: alpha (blocks 0-1023) + input transform V ----------------
__global__ void prepB_kernel(const float* __restrict__ x) {
    if (blockIdx.x < 1024) {
        int warp = (blockIdx.x * 256 + threadIdx.x) >> 5;
        int lane = threadIdx.x & 31;
        int b = warp >> 9, co = warp & 511;
        float sum = 0.f;
        const float* w2 = g_W2 + co * 512;
        const float* sv = g_s + b * 512;
        for (int ci = lane; ci < 512; ci += 32) {
            float s = sv[ci];
            sum += w2[ci] * s * s;
        }
        #pragma unroll
        for (int off = 16; off > 0; off >>= 1) sum += __shfl_xor_sync(0xffffffffu, sum, off);
        if (lane == 0)
            g_alpha[b * 512 + co] = CONV_SCALE / sqrtf(CONV_SCALE * CONV_SCALE * sum + 1e-8f);
        return;
    }
    __shared__ float smx[4][66][33];
    __shared__ float ss[32];
    int id = blockIdx.x - 1024;                 // 8192 blocks
    int ty = id & 31, ci0 = ((id >> 5) & 15) * 32, b = id >> 9;
    int tid = threadIdx.x;
    for (int k = tid; k < 4 * 66 * 33; k += 256) (&smx[0][0][0])[k] = 0.f;
    if (tid < 32) ss[tid] = g_s[b * 512 + ci0 + tid];
    __syncthreads();
    {
        int i = tid >> 3, r = tid & 7;
        int yl = r >> 1, xh = (r & 1) * 32;
        int ygl = 2 * ty - 1 + yl;
        if (ygl >= 0 && ygl < 64) {
            float s = ss[i];
            const float4* src = reinterpret_cast<const float4*>(
                x + ((size_t)(b * 512 + ci0 + i) * 64 + ygl) * 64 + xh);
            #pragma unroll
            for (int k = 0; k < 8; k++) {
                float4 f = src[k];
                int c = xh + k * 4 + 1;
                smx[yl][c + 0][i] = f.x * s;
                smx[yl][c + 1][i] = f.y * s;
                smx[yl][c + 2][i] = f.z * s;
                smx[yl][c + 3][i] = f.w * s;
            }
        }
    }
    __syncthreads();
    int lane = tid & 31, w = tid >> 5;
    size_t tbase = ((size_t)(b * 32 + ty)) * 32;
    #pragma unroll
    for (int it = 0; it < 4; it++) {
        int tx = w + it * 8;
        float d[4][4];
        #pragma unroll
        for (int i = 0; i < 4; i++)
            #pragma unroll
            for (int j = 0; j < 4; j++)
                d[i][j] = smx[i][2 * tx + j][lane];
        float e[4][4];
        #pragma unroll
        for (int j = 0; j < 4; j++) {
            e[0][j] = d[0][j] - d[2][j];
            e[1][j] = d[1][j] + d[2][j];
            e[2][j] = d[2][j] - d[1][j];
            e[3][j] = d[1][j] - d[3][j];
        }
        size_t vofs = (tbase + tx) * 512 + ci0 + lane;
        #pragma unroll
        for (int i = 0; i < 4; i++) {
            float v0 = e[i][0] - e[i][2];
            float v1 = e[i][1] + e[i][2];
            float v2 = e[i][2] - e[i][1];
            float v3 = e[i][1] - e[i][3];
            g_V[(size_t)(i * 4 + 0) * VPLANE + vofs] = __float2half(v0);
            g_V[(size_t)(i * 4 + 1) * VPLANE + vofs] = __float2half(v1);
            g_V[(size_t)(i * 4 + 2) * VPLANE + vofs] = __float2half(v2);
            g_V[(size_t)(i * 4 + 3) * VPLANE + vofs] = __float2half(v3);
        }
    }
}

// ================= GEMM kernel: 8 stages of kc=64, 4-deep smem ring =================
// CTA: 128 co x 256 tiles, one plane. 8 warps = 4m x 2n (R13 tiles).
// fill(s+3) issued after compute(s): ~3 stages of latency tolerance per fill.
// Fill is 3072 cp.async of 16B per stage (B: 256x8, A: 128x8) — COMPLETE kc=64 coverage.

#define GSTRIDE 72                     /* halfs; 144B rows, 16B-aligned, LDSM conflict-free */
#define GB_BYTES (256 * GSTRIDE * 2)   /* 36864 */
#define GA_BYTES (128 * GSTRIDE * 2)   /* 18432 */
#define GSTG (GB_BYTES + GA_BYTES)     /* 55296 */
#define GSMEM (4 * GSTG)               /* 221184 */

__device__ __forceinline__ void cp16(uint32_t dst, const void* src, int sz) {
    asm volatile("cp.async.cg.shared.global [%0], [%1], 16, %2;"
                 :: "r"(dst), "l"(src), "r"(sz) : "memory");
}
__device__ __forceinline__ void cp_commit() {
    asm volatile("cp.async.commit_group;" ::: "memory");
}
__device__ __forceinline__ void ldsm4(uint32_t r[4], uint32_t addr) {
    asm volatile("ldmatrix.sync.aligned.m8n8.x4.shared.b16 {%0,%1,%2,%3}, [%4];"
                 : "=r"(r[0]), "=r"(r[1]), "=r"(r[2]), "=r"(r[3]) : "r"(addr));
}
__device__ __forceinline__ void mma_f16(float acc[4], const uint32_t a[4], const uint32_t b2[2]) {
    asm volatile(
        "mma.sync.aligned.m16n8k16.row.col.f32.f16.f16.f32 "
        "{%0,%1,%2,%3}, {%4,%5,%6,%7}, {%8,%9}, {%0,%1,%2,%3};\n"
        : "+f"(acc[0]), "+f"(acc[1]), "+f"(acc[2]), "+f"(acc[3])
        : "r"(a[0]), "r"(a[1]), "r"(a[2]), "r"(a[3]), "r"(b2[0]), "r"(b2[1]));
}

__global__ void __launch_bounds__(256, 1) gemm_kernel() {
    extern __shared__ __align__(16) __half sh[];
    const uint32_t sbase = (uint32_t)__cvta_generic_to_shared(sh);

    const int tid = threadIdx.x, lane = tid & 31, warp = tid >> 5;
    const int wm = warp & 3, wn = warp >> 2;
    const int p = blockIdx.z, co0 = blockIdx.x * 128, n0 = blockIdx.y * 256;

    const __half* Vp = g_V + (size_t)p * VPLANE;
    const __half* Up = g_U + (size_t)p * 262144;

    // fill stage s (64 ci) into ring slot s&3; 3072 cps (12 per thread, exact)
    auto fill = [&](int s) {
        uint32_t bb_ = sbase + (uint32_t)(s & 3) * GSTG;
        uint32_t ab_ = bb_ + GB_BYTES;
        int ofs = s * 64;
        #pragma unroll
        for (int it = 0; it < 12; it++) {
            int idx = tid + it * 256;
            if (idx < 2048) {                       // B: 256 rows x 8 cp
                int row = idx >> 3, v = idx & 7;
                cp16(bb_ + (uint32_t)(row * GSTRIDE + v * 8) * 2,
                     Vp + (size_t)(n0 + row) * 512 + ofs + v * 8, 16);
            } else {                                // A: 128 rows x 8 cp
                int j = idx - 2048;
                int row = j >> 3, v = j & 7;
                cp16(ab_ + (uint32_t)(row * GSTRIDE + v * 8) * 2,
                     Up + (size_t)(co0 + row) * 512 + ofs + v * 8, 16);
            }
        }
        cp_commit();
    };

    const int l15 = ((lane >> 3) & 1) * 8 + (lane & 7);
    const int aK  = (lane >> 4) * 8;
    uint32_t aBase[2];
    #pragma unroll
    for (int mf = 0; mf < 2; mf++)
        aBase[mf] = (uint32_t)(((wm * 32 + mf * 16 + l15) * GSTRIDE + aK) * 2);
    const int nloc = ((lane >> 4) & 1) * 8 + (lane & 7);
    const int bK   = ((lane >> 3) & 1) * 8;
    uint32_t bBase[8];
    #pragma unroll
    for (int nfp = 0; nfp < 8; nfp++)
        bBase[nfp] = (uint32_t)(((wn * 128 + nfp * 16 + nloc) * GSTRIDE + bK) * 2);

    float acc[2][16][4];
    #pragma unroll
    for (int mf = 0; mf < 2; mf++)
        #pragma unroll
        for (int nf = 0; nf < 16; nf++)
            #pragma unroll
            for (int i = 0; i < 4; i++) acc[mf][nf][i] = 0.f;

    fill(0);
    fill(1);
    fill(2);

    for (int s = 0; s < 8; s++) {
        // need fill(s) complete; younger outstanding groups = min(2, 7-s)
        if (s <= 5)      asm volatile("cp.async.wait_group 2;" ::: "memory");
        else if (s == 6) asm volatile("cp.async.wait_group 1;" ::: "memory");
        else             asm volatile("cp.async.wait_group 0;" ::: "memory");
        __syncthreads();

        const uint32_t bB = sbase + (uint32_t)(s & 3) * GSTG;
        const uint32_t aB = bB + GB_BYTES;

        #define AOFS(t, h) (aB + aBase[h] + (uint32_t)((t) * 32))
        #define BOFS(t, nfp) (bB + bBase[nfp] + (uint32_t)((t) * 32))

        uint32_t aa[2][2][4];
        uint32_t bb[2][4];
        ldsm4(aa[0][0], AOFS(0, 0));
        ldsm4(aa[0][1], AOFS(0, 1));
        ldsm4(bb[0], BOFS(0, 0));

        #pragma unroll
        for (int t = 0; t < 4; t++) {              // 4 k-steps of 16 ci
            const int ct = t & 1, nt = ct ^ 1;
            if (t < 3) {
                ldsm4(aa[nt][0], AOFS(t + 1, 0));
                ldsm4(aa[nt][1], AOFS(t + 1, 1));
            }
            #pragma unroll
            for (int nfp = 0; nfp < 8; nfp++) {
                const int cb = nfp & 1, nb = cb ^ 1;
                if (nfp < 7)     ldsm4(bb[nb], BOFS(t, nfp + 1));
                else if (t < 3)  ldsm4(bb[nb], BOFS(t + 1, 0));
                mma_f16(acc[0][2 * nfp],     aa[ct][0], bb[cb]);
                mma_f16(acc[0][2 * nfp + 1], aa[ct][0], bb[cb] + 2);
                mma_f16(acc[1][2 * nfp],     aa[ct][1], bb[cb]);
                mma_f16(acc[1][2 * nfp + 1], aa[ct][1], bb[cb] + 2);
            }
        }
        #undef AOFS
        #undef BOFS

        __syncthreads();
        if (s + 3 < 8) fill(s + 3);
    }

    // epilogue: M[p][co][tile] fp16 (half2 stores)
    __half* Mp = g_M + (size_t)p * MPLANE;
    #pragma unroll
    for (int mf = 0; mf < 2; mf++) {
        int co = co0 + wm * 32 + mf * 16 + (lane >> 2);
        __half* m0 = Mp + (size_t)co * 16384;
        __half* m1 = m0 + 8 * 16384;
        #pragma unroll
        for (int nf = 0; nf < 16; nf++) {
            int tile = n0 + wn * 128 + nf * 8 + (lane & 3) * 2;
            *reinterpret_cast<__half2*>(m0 + tile) =
                __floats2half2_rn(acc[mf][nf][0], acc[mf][nf][1]);
            *reinterpret_cast<__half2*>(m1 + tile) =
                __floats2half2_rn(acc[mf][nf][2], acc[mf][nf][3]);
        }
    }
}

// ---------------- output transform: y = A^T M A (fp16 M, tile-pairs via half2) ----------------
__global__ void outT_kernel(float* __restrict__ out) {
    int id = blockIdx.x * 256 + threadIdx.x;    // 4.2M threads (tile pairs)
    int txp = id & 15, ty = (id >> 4) & 31, b = (id >> 9) & 15, co = id >> 13;
    size_t mo = (size_t)co * 16384 + ((size_t)(b * 32 + ty)) * 32 + 2 * txp;
    float2 m[16];
    #pragma unroll
    for (int q = 0; q < 16; q++)
        m[q] = __half22float2(*reinterpret_cast<const __half2*>(g_M + (size_t)q * MPLANE + mo));
    float a = g_alpha[b * 512 + co];
    float4 row0, row1;
    {
        float s0[4], s1[4];
        #pragma unroll
        for (int j = 0; j < 4; j++) {
            s0[j] = m[j].x + m[4 + j].x + m[8 + j].x;
            s1[j] = m[4 + j].x - m[8 + j].x - m[12 + j].x;
        }
        row0.x = a * (s0[0] + s0[1] + s0[2]); row0.y = a * (s0[1] - s0[2] - s0[3]);
        row1.x = a * (s1[0] + s1[1] + s1[2]); row1.y = a * (s1[1] - s1[2] - s1[3]);
    }
    {
        float s0[4], s1[4];
        #pragma unroll
        for (int j = 0; j < 4; j++) {
            s0[j] = m[j].y + m[4 + j].y + m[8 + j].y;
            s1[j] = m[4 + j].y - m[8 + j].y - m[12 + j].y;
        }
        row0.z = a * (s0[0] + s0[1] + s0[2]); row0.w = a * (s0[1] - s0[2] - s0[3]);
        row1.z = a * (s1[0] + s1[1] + s1[2]); row1.w = a * (s1[1] - s1[2] - s1[3]);
    }
    float* o = out + (((size_t)(b * 512 + co) * 64 + 2 * ty) * 64 + 4 * txp);
    *reinterpret_cast<float4*>(o)      = row0;
    *reinterpret_cast<float4*>(o + 64) = row1;
}

// ---------------- launch ----------------
extern "C" void kernel_launch(void* const* d_in, const int* in_sizes, int n_in,
                              void* d_out, int out_size) {
    const float* x     = (const float*)d_in[0];
    const float* style = (const float*)d_in[1];
    const float* weight= (const float*)d_in[2];
    const float* mw    = (const float*)d_in[3];
    const float* mbias = (const float*)d_in[4];
    float* out = (float*)d_out;
    (void)in_sizes; (void)n_in; (void)out_size;

    cudaFuncSetAttribute(gemm_kernel, cudaFuncAttributeMaxDynamicSharedMemorySize, GSMEM);

    prepA_kernel<<<2048, 256>>>(style, mw, mbias, weight);
    prepB_kernel<<<1024 + 8192, 256>>>(x);
    gemm_kernel<<<dim3(4, 64, 16), 256, GSMEM>>>();
    outT_kernel<<<16384, 256>>>(out);
}